// round 6
// baseline (speedup 1.0000x reference)
#include <cuda_runtime.h>

// 2-layer LSTM (H=51), B=512, T=512, scalar in, linear head, future=0.
// 128 persistent blocks, BB=4 rows, 640 threads (20 warps = 5/SMSP), 1 barrier/step.
// Thread = 2 gates x 4 batches x k-half; weights in regs (28 f32x2);
// xor-1 k-reduce -> (L2: xor-4 matrix-reduce) -> xor-2 gate exchange -> 1 cell/thread.
// Layer-2 lags layer-1 by one step; h double-buffered by parity.

#define H    51
#define HP   56
#define TT   512
#define NTH  640
#define NBLK 128
#define NITER 514

typedef unsigned long long ull;

__device__ __forceinline__ ull fma2(ull a, ull b, ull c) {
    ull d; asm("fma.rn.f32x2 %0, %1, %2, %3;" : "=l"(d) : "l"(a), "l"(b), "l"(c)); return d;
}
__device__ __forceinline__ ull pack2(float lo, float hi) {
    ull d; asm("mov.b64 %0, {%1, %2};" : "=l"(d) : "f"(lo), "f"(hi)); return d;
}
__device__ __forceinline__ float sum2(ull a) {
    float x, y; asm("mov.b64 {%0, %1}, %2;" : "=f"(x), "=f"(y) : "l"(a)); return x + y;
}
__device__ __forceinline__ float sigf(float x)     { return 1.0f / (1.0f + __expf(-x)); }
__device__ __forceinline__ float tanhfast(float x) { return 1.0f - 2.0f / (__expf(2.0f*x) + 1.0f); }

__global__ __launch_bounds__(NTH, 1)
void lstm2_kernel(const float* __restrict__ input,
                  const float* __restrict__ W_ih1,
                  const float* __restrict__ W_hh1,
                  const float* __restrict__ b_ih1,
                  const float* __restrict__ b_hh1,
                  const float* __restrict__ W_ih2,
                  const float* __restrict__ W_hh2,
                  const float* __restrict__ b_ih2,
                  const float* __restrict__ b_hh2,
                  const float* __restrict__ W_lin,
                  const float* __restrict__ b_lin,
                  float* __restrict__ out)
{
    // h1 parity0/1 [224 each], pad[8] (h2 base == 8 mod 32 banks), h2 parity0/1
    __shared__ __align__(16) float hbuf[2*4*HP + 8 + 2*4*HP];
    __shared__ float xall[4*TT];

    float* const h1b = hbuf;
    float* const h2b = hbuf + 2*4*HP + 8;

    const int tid  = threadIdx.x;
    const int lane = tid & 31;
    const int row0 = blockIdx.x * 4;

    const bool isL1  = (tid < 204);
    const bool isOut = (tid >= 204 && tid < 212);
    const bool isL2  = (tid >= 224 && tid < 632);

    // ---- init smem ----
    for (int i = tid; i < 2*4*HP + 8 + 2*4*HP; i += NTH) hbuf[i] = 0.0f;
    for (int i = tid; i < 4*TT; i += NTH) {
        const int b = i >> 9;
        const int t = i & (TT - 1);
        xall[i] = input[(row0 + b)*TT + t];
    }

    // ---- role decode ----
    int unit = 0, gp = 0, ks = 0, mat = 0;
    if (isL1)      { unit = tid >> 2; gp = (tid >> 1) & 1; ks = tid & 1; }
    else if (isL2) { const int l2 = tid - 224; unit = l2 >> 3; mat = (l2 >> 2) & 1;
                     gp = (l2 >> 1) & 1; ks = l2 & 1; }

    // ---- weights -> registers: 2 gate rows (2gp+e) x k-half as f32x2 ----
    ull w2[2][14];
    float bz[2] = {0.f, 0.f}, wx[2] = {0.f, 0.f};
    if (isL1 || isL2) {
        const float* W = isL1 ? W_hh1 : (mat ? W_hh2 : W_ih2);
        #pragma unroll
        for (int e = 0; e < 2; ++e) {
            const int r = unit + 51*(2*gp + e);
            #pragma unroll
            for (int m = 0; m < 14; ++m) {
                const int k = ks*28 + 2*m;
                const float lo = (k   < H) ? W[r*H + k]     : 0.0f;
                const float hi = (k+1 < H) ? W[r*H + k + 1] : 0.0f;
                w2[e][m] = pack2(lo, hi);
            }
            if (isL1) { bz[e] = b_ih1[r] + b_hh1[r]; wx[e] = W_ih1[r]; }
            else      { bz[e] = b_ih2[r] + b_hh2[r]; }
        }
    }

    // ---- out-head (warp 6, lanes 12..19): pair (batch, half-of-26) ----
    float wo[26]; float blin = 0.0f; int ob = 0, half = 0;
    if (isOut) {
        const int o = tid - 204;
        ob = o >> 1; half = o & 1;
        #pragma unroll
        for (int m = 0; m < 26; ++m) {
            const int j = half*26 + m;
            wo[m] = (j < H) ? W_lin[j] : 0.0f;
        }
        blin = b_lin[0];
    }

    const unsigned pmask = 0x3u  << (lane & 30);   // xor-1 pair
    const unsigned qmask = 0xFu  << (lane & 28);   // xor-2 quad
    const unsigned omask = 0xFFu << (lane & 24);   // xor-4 octet

    float cst = 0.f;    // cell state: L1 all threads, L2 mat==0 threads
    __syncthreads();

    for (int t = 0; t < NITER; ++t) {
        const int p = t & 1;
        float* const h1r = h1b + p*(4*HP);
        float* const h1w = h1b + (p^1)*(4*HP);
        float* const h2r = h2b + p*(4*HP);
        float* const h2w = h2b + (p^1)*(4*HP);

        if (isL1) {
            if (t < TT) {
                ull acc[2][4];
                #pragma unroll
                for (int e = 0; e < 2; ++e)
                    { acc[e][0]=0ull; acc[e][1]=0ull; acc[e][2]=0ull; acc[e][3]=0ull; }
                const float* hp = h1r + ks*28;
                #pragma unroll
                for (int j = 0; j < 7; ++j) {
                    const ulonglong2 u0 = *reinterpret_cast<const ulonglong2*>(hp + 0*HP + 4*j);
                    const ulonglong2 u1 = *reinterpret_cast<const ulonglong2*>(hp + 1*HP + 4*j);
                    const ulonglong2 u2 = *reinterpret_cast<const ulonglong2*>(hp + 2*HP + 4*j);
                    const ulonglong2 u3 = *reinterpret_cast<const ulonglong2*>(hp + 3*HP + 4*j);
                    #pragma unroll
                    for (int e = 0; e < 2; ++e) {
                        acc[e][0] = fma2(w2[e][2*j],   u0.x, acc[e][0]);
                        acc[e][0] = fma2(w2[e][2*j+1], u0.y, acc[e][0]);
                        acc[e][1] = fma2(w2[e][2*j],   u1.x, acc[e][1]);
                        acc[e][1] = fma2(w2[e][2*j+1], u1.y, acc[e][1]);
                        acc[e][2] = fma2(w2[e][2*j],   u2.x, acc[e][2]);
                        acc[e][2] = fma2(w2[e][2*j+1], u2.y, acc[e][2]);
                        acc[e][3] = fma2(w2[e][2*j],   u3.x, acc[e][3]);
                        acc[e][3] = fma2(w2[e][2*j+1], u3.y, acc[e][3]);
                    }
                }
                // xor-1 k-reduce; ks0 keeps batches {0,1}, ks1 keeps {2,3}
                float z[2][2];
                #pragma unroll
                for (int e = 0; e < 2; ++e)
                    #pragma unroll
                    for (int lb = 0; lb < 2; ++lb) {
                        const float mine  = sum2(ks ? acc[e][2+lb] : acc[e][lb]);
                        const float other = sum2(ks ? acc[e][lb]   : acc[e][2+lb]);
                        z[e][lb] = mine + __shfl_xor_sync(pmask, other, 1);
                    }
                // add bias + x-term (per batch slot) BEFORE gate exchange
                #pragma unroll
                for (int lb = 0; lb < 2; ++lb) {
                    const float xv = xall[(2*ks + lb)*TT + t];
                    #pragma unroll
                    for (int e = 0; e < 2; ++e)
                        z[e][lb] += fmaf(xv, wx[e], bz[e]);
                }
                // xor-2 gate exchange: my batch slot = gp; send slot gp^1
                const float r0 = __shfl_xor_sync(qmask, gp ? z[0][0] : z[0][1], 2);
                const float r1 = __shfl_xor_sync(qmask, gp ? z[1][0] : z[1][1], 2);
                const float m0 = gp ? z[0][1] : z[0][0];
                const float m1 = gp ? z[1][1] : z[1][0];
                const float zi = gp ? r0 : m0;
                const float zf = gp ? r1 : m1;
                const float zg = gp ? m0 : r0;
                const float zo = gp ? m1 : r1;
                const float ig = sigf(zi), fg = sigf(zf);
                const float gg = tanhfast(zg), og = sigf(zo);
                cst = fmaf(fg, cst, ig*gg);
                h1w[(2*ks + gp)*HP + unit] = og * tanhfast(cst);
            }
        } else if (isL2) {
            if (t >= 1 && t <= TT) {
                ull acc[2][4];
                #pragma unroll
                for (int e = 0; e < 2; ++e)
                    { acc[e][0]=0ull; acc[e][1]=0ull; acc[e][2]=0ull; acc[e][3]=0ull; }
                const float* hp = (mat ? h2r : h1r) + ks*28;
                #pragma unroll
                for (int j = 0; j < 7; ++j) {
                    const ulonglong2 u0 = *reinterpret_cast<const ulonglong2*>(hp + 0*HP + 4*j);
                    const ulonglong2 u1 = *reinterpret_cast<const ulonglong2*>(hp + 1*HP + 4*j);
                    const ulonglong2 u2 = *reinterpret_cast<const ulonglong2*>(hp + 2*HP + 4*j);
                    const ulonglong2 u3 = *reinterpret_cast<const ulonglong2*>(hp + 3*HP + 4*j);
                    #pragma unroll
                    for (int e = 0; e < 2; ++e) {
                        acc[e][0] = fma2(w2[e][2*j],   u0.x, acc[e][0]);
                        acc[e][0] = fma2(w2[e][2*j+1], u0.y, acc[e][0]);
                        acc[e][1] = fma2(w2[e][2*j],   u1.x, acc[e][1]);
                        acc[e][1] = fma2(w2[e][2*j+1], u1.y, acc[e][1]);
                        acc[e][2] = fma2(w2[e][2*j],   u2.x, acc[e][2]);
                        acc[e][2] = fma2(w2[e][2*j+1], u2.y, acc[e][2]);
                        acc[e][3] = fma2(w2[e][2*j],   u3.x, acc[e][3]);
                        acc[e][3] = fma2(w2[e][2*j+1], u3.y, acc[e][3]);
                    }
                }
                // xor-1 k-reduce
                float z[2][2];
                #pragma unroll
                for (int e = 0; e < 2; ++e)
                    #pragma unroll
                    for (int lb = 0; lb < 2; ++lb) {
                        const float mine  = sum2(ks ? acc[e][2+lb] : acc[e][lb]);
                        const float other = sum2(ks ? acc[e][lb]   : acc[e][2+lb]);
                        z[e][lb] = mine + __shfl_xor_sync(pmask, other, 1);
                    }
                // xor-4 matrix-reduce (both mats get full sums)
                #pragma unroll
                for (int e = 0; e < 2; ++e)
                    #pragma unroll
                    for (int lb = 0; lb < 2; ++lb)
                        z[e][lb] += __shfl_xor_sync(omask, z[e][lb], 4);
                // bias (once, on every final path; both mats hold same z; only mat0 commits)
                #pragma unroll
                for (int lb = 0; lb < 2; ++lb)
                    #pragma unroll
                    for (int e = 0; e < 2; ++e)
                        z[e][lb] += bz[e];
                // xor-2 gate exchange (within same mat)
                const float r0 = __shfl_xor_sync(qmask, gp ? z[0][0] : z[0][1], 2);
                const float r1 = __shfl_xor_sync(qmask, gp ? z[1][0] : z[1][1], 2);
                if (mat == 0) {
                    const float m0 = gp ? z[0][1] : z[0][0];
                    const float m1 = gp ? z[1][1] : z[1][0];
                    const float zi = gp ? r0 : m0;
                    const float zf = gp ? r1 : m1;
                    const float zg = gp ? m0 : r0;
                    const float zo = gp ? m1 : r1;
                    const float ig = sigf(zi), fg = sigf(zf);
                    const float gg = tanhfast(zg), og = sigf(zo);
                    cst = fmaf(fg, cst, ig*gg);
                    h2w[(2*ks + gp)*HP + unit] = og * tanhfast(cst);
                }
            }
        } else if (isOut) {
            if (t >= 2) {
                float v = 0.f;
                #pragma unroll
                for (int m = 0; m < 26; ++m)
                    v = fmaf(h2r[ob*HP + half*26 + m], wo[m], v);
                v += __shfl_xor_sync(pmask, v, 1);
                if (half == 0) out[(row0 + ob)*TT + (t - 2)] = v + blin;
            }
        }
        __syncthreads();
    }
}

extern "C" void kernel_launch(void* const* d_in, const int* in_sizes, int n_in,
                              void* d_out, int out_size)
{
    const float* input = (const float*)d_in[0];
    const float* W_ih1 = (const float*)d_in[1];
    const float* W_hh1 = (const float*)d_in[2];
    const float* b_ih1 = (const float*)d_in[3];
    const float* b_hh1 = (const float*)d_in[4];
    const float* W_ih2 = (const float*)d_in[5];
    const float* W_hh2 = (const float*)d_in[6];
    const float* b_ih2 = (const float*)d_in[7];
    const float* b_hh2 = (const float*)d_in[8];
    const float* W_lin = (const float*)d_in[9];
    const float* b_lin = (const float*)d_in[10];
    float* out = (float*)d_out;

    lstm2_kernel<<<NBLK, NTH>>>(input, W_ih1, W_hh1, b_ih1, b_hh1,
                                W_ih2, W_hh2, b_ih2, b_hh2,
                                W_lin, b_lin, out);
}

// round 7
// speedup vs baseline: 1.1124x; 1.1124x over previous
#include <cuda_runtime.h>

// 2-layer LSTM (H=51), B=512, T=512, scalar in, linear head, future=0.
// 128 persistent blocks, BB=4 rows, 352 threads.
// DECOUPLED warp groups: L1 producer (warps 0-3) and L2 consumer (warps 4-10,
// incl. out-head) run asynchronously over a depth-2 h1 ring, synchronized by
// named barriers (bar.arrive / bar.sync). Compute tiling identical to R5:
// thread = 4 gates x 4 batches x k-half, weights in registers, f32x2 FMAs.

#define H    51
#define HP   56
#define BHP  (4*HP)
#define TT   512
#define NTH  352
#define NBLK 128

#define BAR_FULL0  1
#define BAR_FULL1  2
#define BAR_EMPTY0 3
#define BAR_EMPTY1 4
#define BAR_CNT    352

typedef unsigned long long ull;

__device__ __forceinline__ void bar_sync_n(int id) {
    asm volatile("bar.sync %0, %1;" :: "r"(id), "r"(BAR_CNT) : "memory");
}
__device__ __forceinline__ void bar_arrive_n(int id) {
    asm volatile("bar.arrive %0, %1;" :: "r"(id), "r"(BAR_CNT) : "memory");
}

__device__ __forceinline__ ull fma2(ull a, ull b, ull c) {
    ull d; asm("fma.rn.f32x2 %0, %1, %2, %3;" : "=l"(d) : "l"(a), "l"(b), "l"(c)); return d;
}
__device__ __forceinline__ ull pack2(float lo, float hi) {
    ull d; asm("mov.b64 %0, {%1, %2};" : "=l"(d) : "f"(lo), "f"(hi)); return d;
}
__device__ __forceinline__ float sum2(ull a) {
    float x, y; asm("mov.b64 {%0, %1}, %2;" : "=f"(x), "=f"(y) : "l"(a)); return x + y;
}
__device__ __forceinline__ float sigf(float x)     { return 1.0f / (1.0f + __expf(-x)); }
__device__ __forceinline__ float tanhfast(float x) { return 1.0f - 2.0f / (__expf(2.0f*x) + 1.0f); }

__global__ __launch_bounds__(NTH, 1)
void lstm2_kernel(const float* __restrict__ input,
                  const float* __restrict__ W_ih1,
                  const float* __restrict__ W_hh1,
                  const float* __restrict__ b_ih1,
                  const float* __restrict__ b_hh1,
                  const float* __restrict__ W_ih2,
                  const float* __restrict__ W_hh2,
                  const float* __restrict__ b_ih2,
                  const float* __restrict__ b_hh2,
                  const float* __restrict__ W_lin,
                  const float* __restrict__ b_lin,
                  float* __restrict__ out)
{
    // h1 parity0/1, pad 8 floats (bank offset), h2 parity0/1
    __shared__ __align__(16) float hbuf[2*BHP + 8 + 2*BHP];
    __shared__ float xall[4*TT];

    float* const h1b = hbuf;
    float* const h2b = hbuf + 2*BHP + 8;

    const int tid  = threadIdx.x;
    const int lane = tid & 31;
    const int row0 = blockIdx.x * 4;

    const unsigned pmask = 0x3u << (lane & 30);
    const unsigned qmask = 0xFu << (lane & 28);

    // ---- init smem ----
    for (int i = tid; i < 2*BHP + 8 + 2*BHP; i += NTH) hbuf[i] = 0.0f;
    for (int i = tid; i < 4*TT; i += NTH) {
        const int b = i >> 9;
        const int t = i & (TT - 1);
        xall[i] = input[(row0 + b)*TT + t];
    }

    if (tid < 128) {
        // ================= L1 PRODUCER GROUP (warps 0-3) =================
        const bool act = (tid < 102);
        const int unit = tid >> 1;
        const int ks   = tid & 1;

        ull w2[4][14];
        float bz[4] = {0,0,0,0}, wx[4] = {0,0,0,0};
        if (act) {
            #pragma unroll
            for (int g = 0; g < 4; ++g) {
                const int r = unit + 51*g;
                #pragma unroll
                for (int m = 0; m < 14; ++m) {
                    const int k = ks*28 + 2*m;
                    const float lo = (k   < H) ? W_hh1[r*H + k]     : 0.0f;
                    const float hi = (k+1 < H) ? W_hh1[r*H + k + 1] : 0.0f;
                    w2[g][m] = pack2(lo, hi);
                }
                bz[g] = b_ih1[r] + b_hh1[r];
                wx[g] = W_ih1[r];
            }
        }
        float c1[2] = {0.f, 0.f};

        __syncthreads();   // init visibility (all 352 threads)

        for (int t = 0; t < 513; ++t) {
            const int s = t & 1;
            bar_sync_n(s ? BAR_EMPTY1 : BAR_EMPTY0);   // L2 done with h1(t-2)
            if (act && t < TT) {
                const float* h1r = h1b + (s^1)*BHP;    // h1(t-1)
                float*       h1w = h1b + s*BHP;        // h1(t)
                ull acc[4][4];
                #pragma unroll
                for (int g = 0; g < 4; ++g)
                    { acc[g][0]=0ull; acc[g][1]=0ull; acc[g][2]=0ull; acc[g][3]=0ull; }
                const float* hp = h1r + ks*28;
                #pragma unroll
                for (int j = 0; j < 7; ++j) {
                    const ulonglong2 u0 = *reinterpret_cast<const ulonglong2*>(hp + 0*HP + 4*j);
                    const ulonglong2 u1 = *reinterpret_cast<const ulonglong2*>(hp + 1*HP + 4*j);
                    const ulonglong2 u2 = *reinterpret_cast<const ulonglong2*>(hp + 2*HP + 4*j);
                    const ulonglong2 u3 = *reinterpret_cast<const ulonglong2*>(hp + 3*HP + 4*j);
                    #pragma unroll
                    for (int g = 0; g < 4; ++g) {
                        acc[g][0] = fma2(w2[g][2*j],   u0.x, acc[g][0]);
                        acc[g][0] = fma2(w2[g][2*j+1], u0.y, acc[g][0]);
                        acc[g][1] = fma2(w2[g][2*j],   u1.x, acc[g][1]);
                        acc[g][1] = fma2(w2[g][2*j+1], u1.y, acc[g][1]);
                        acc[g][2] = fma2(w2[g][2*j],   u2.x, acc[g][2]);
                        acc[g][2] = fma2(w2[g][2*j+1], u2.y, acc[g][2]);
                        acc[g][3] = fma2(w2[g][2*j],   u3.x, acc[g][3]);
                        acc[g][3] = fma2(w2[g][2*j+1], u3.y, acc[g][3]);
                    }
                }
                float fin[4][2];
                #pragma unroll
                for (int g = 0; g < 4; ++g)
                    #pragma unroll
                    for (int lb = 0; lb < 2; ++lb) {
                        const float mine  = sum2(ks ? acc[g][2+lb] : acc[g][lb]);
                        const float other = sum2(ks ? acc[g][lb]   : acc[g][2+lb]);
                        fin[g][lb] = mine + __shfl_xor_sync(pmask, other, 1);
                    }
                #pragma unroll
                for (int lb = 0; lb < 2; ++lb) {
                    const int b = 2*ks + lb;
                    const float xv = xall[b*TT + t];
                    const float zi = fmaf(xv, wx[0], fin[0][lb] + bz[0]);
                    const float zf = fmaf(xv, wx[1], fin[1][lb] + bz[1]);
                    const float zg = fmaf(xv, wx[2], fin[2][lb] + bz[2]);
                    const float zo = fmaf(xv, wx[3], fin[3][lb] + bz[3]);
                    const float ig = sigf(zi), fg = sigf(zf);
                    const float gg = tanhfast(zg), og = sigf(zo);
                    c1[lb] = fmaf(fg, c1[lb], ig*gg);
                    h1w[b*HP + unit] = og * tanhfast(c1[lb]);
                }
            }
            bar_arrive_n(s ? BAR_FULL1 : BAR_FULL0);   // h1(t) published
        }
    } else {
        // ================= L2 CONSUMER GROUP (warps 4-10) =================
        const int  l2    = tid - 128;
        const bool act   = (l2 < 204);
        const bool isOut = (tid >= 332 && tid < 340);
        const int  unit  = l2 >> 2;
        const int  mat   = (l2 >> 1) & 1;
        const int  ks    = l2 & 1;

        ull w2[4][14];
        float bz[4] = {0,0,0,0};
        if (act) {
            const float* W = mat ? W_hh2 : W_ih2;
            #pragma unroll
            for (int g = 0; g < 4; ++g) {
                const int r = unit + 51*g;
                #pragma unroll
                for (int m = 0; m < 14; ++m) {
                    const int k = ks*28 + 2*m;
                    const float lo = (k   < H) ? W[r*H + k]     : 0.0f;
                    const float hi = (k+1 < H) ? W[r*H + k + 1] : 0.0f;
                    w2[g][m] = pack2(lo, hi);
                }
                bz[g] = b_ih2[r] + b_hh2[r];
            }
        }
        float c2 = 0.f;

        float wo[26]; float blin = 0.0f; int ob = 0, half = 0;
        if (isOut) {
            const int o = tid - 332;
            ob = o >> 1; half = o & 1;
            #pragma unroll
            for (int m = 0; m < 26; ++m) {
                const int j = half*26 + m;
                wo[m] = (j < H) ? W_lin[j] : 0.0f;
            }
            blin = b_lin[0];
        }

        __syncthreads();   // init visibility (all 352 threads)

        // pre-seed the EMPTY barriers so L1's first two waits pass
        bar_arrive_n(BAR_EMPTY0);
        bar_arrive_n(BAR_EMPTY1);

        for (int t = 0; t < 513; ++t) {
            const int s = t & 1;
            bar_sync_n(s ? BAR_FULL1 : BAR_FULL0);     // h1(t) ready; L2 rendezvous
            if (act && t < TT) {
                const float* h1r = h1b + s*BHP;        // h1(t)
                const float* h2r = h2b + (s^1)*BHP;    // h2(t-1)
                float*       h2w = h2b + s*BHP;        // h2(t)
                ull acc[4][4];
                #pragma unroll
                for (int g = 0; g < 4; ++g)
                    { acc[g][0]=0ull; acc[g][1]=0ull; acc[g][2]=0ull; acc[g][3]=0ull; }
                const float* hp = (mat ? h2r : h1r) + ks*28;
                #pragma unroll
                for (int j = 0; j < 7; ++j) {
                    const ulonglong2 u0 = *reinterpret_cast<const ulonglong2*>(hp + 0*HP + 4*j);
                    const ulonglong2 u1 = *reinterpret_cast<const ulonglong2*>(hp + 1*HP + 4*j);
                    const ulonglong2 u2 = *reinterpret_cast<const ulonglong2*>(hp + 2*HP + 4*j);
                    const ulonglong2 u3 = *reinterpret_cast<const ulonglong2*>(hp + 3*HP + 4*j);
                    #pragma unroll
                    for (int g = 0; g < 4; ++g) {
                        acc[g][0] = fma2(w2[g][2*j],   u0.x, acc[g][0]);
                        acc[g][0] = fma2(w2[g][2*j+1], u0.y, acc[g][0]);
                        acc[g][1] = fma2(w2[g][2*j],   u1.x, acc[g][1]);
                        acc[g][1] = fma2(w2[g][2*j+1], u1.y, acc[g][1]);
                        acc[g][2] = fma2(w2[g][2*j],   u2.x, acc[g][2]);
                        acc[g][2] = fma2(w2[g][2*j+1], u2.y, acc[g][2]);
                        acc[g][3] = fma2(w2[g][2*j],   u3.x, acc[g][3]);
                        acc[g][3] = fma2(w2[g][2*j+1], u3.y, acc[g][3]);
                    }
                }
                float fin1[4][2];
                #pragma unroll
                for (int g = 0; g < 4; ++g)
                    #pragma unroll
                    for (int lb = 0; lb < 2; ++lb) {
                        const float mine  = sum2(ks ? acc[g][2+lb] : acc[g][lb]);
                        const float other = sum2(ks ? acc[g][lb]   : acc[g][2+lb]);
                        fin1[g][lb] = mine + __shfl_xor_sync(pmask, other, 1);
                    }
                const int b = 2*ks + mat;
                float zf4[4];
                #pragma unroll
                for (int g = 0; g < 4; ++g) {
                    const float mine  = mat ? fin1[g][1] : fin1[g][0];
                    const float other = mat ? fin1[g][0] : fin1[g][1];
                    zf4[g] = mine + __shfl_xor_sync(qmask, other, 2) + bz[g];
                }
                const float ig = sigf(zf4[0]), fg = sigf(zf4[1]);
                const float gg = tanhfast(zf4[2]), og = sigf(zf4[3]);
                c2 = fmaf(fg, c2, ig*gg);
                h2w[b*HP + unit] = og * tanhfast(c2);
            }
            if (isOut && t >= 1) {
                const float* h2r = h2b + (s^1)*BHP;    // h2(t-1)
                float v = 0.f;
                #pragma unroll
                for (int m = 0; m < 26; ++m)
                    v = fmaf(h2r[ob*HP + half*26 + m], wo[m], v);
                v += __shfl_xor_sync(pmask, v, 1);
                if (half == 0) out[(row0 + ob)*TT + (t - 1)] = v + blin;
            }
            bar_arrive_n(s ? BAR_EMPTY1 : BAR_EMPTY0); // h1(t) consumed
        }
    }
}

extern "C" void kernel_launch(void* const* d_in, const int* in_sizes, int n_in,
                              void* d_out, int out_size)
{
    const float* input = (const float*)d_in[0];
    const float* W_ih1 = (const float*)d_in[1];
    const float* W_hh1 = (const float*)d_in[2];
    const float* b_ih1 = (const float*)d_in[3];
    const float* b_hh1 = (const float*)d_in[4];
    const float* W_ih2 = (const float*)d_in[5];
    const float* W_hh2 = (const float*)d_in[6];
    const float* b_ih2 = (const float*)d_in[7];
    const float* b_hh2 = (const float*)d_in[8];
    const float* W_lin = (const float*)d_in[9];
    const float* b_lin = (const float*)d_in[10];
    float* out = (float*)d_out;

    lstm2_kernel<<<NBLK, NTH>>>(input, W_ih1, W_hh1, b_ih1, b_hh1,
                                W_ih2, W_hh2, b_ih2, b_hh2,
                                W_lin, b_lin, out);
}

// round 8
// speedup vs baseline: 1.2785x; 1.1493x over previous
#include <cuda_runtime.h>

// 2-layer LSTM (H=51), B=512, T=512, scalar in, linear head, future=0.
// 128 persistent blocks, BB=4 rows, 384 threads (12 warps = 3/SMSP).
// R5 compute tiling (thread = 4 gates x 4 batches x k-half, weights in regs,
// f32x2 FMAs, 1 barrier/step, parity-buffered h1/h2, L2 lags L1 by 1 step)
// with SMSP-BALANCED role placement: each SMSP gets ~13 L1 pairs + ~13 L2 quads.
// Activations via tanh.approx.f32.

#define H    51
#define HP   56
#define BHP  (4*HP)
#define TT   512
#define NTH  384
#define NBLK 128
#define NITER 514

typedef unsigned long long ull;

__device__ __forceinline__ ull fma2(ull a, ull b, ull c) {
    ull d; asm("fma.rn.f32x2 %0, %1, %2, %3;" : "=l"(d) : "l"(a), "l"(b), "l"(c)); return d;
}
__device__ __forceinline__ ull pack2(float lo, float hi) {
    ull d; asm("mov.b64 %0, {%1, %2};" : "=l"(d) : "f"(lo), "f"(hi)); return d;
}
__device__ __forceinline__ float sum2(ull a) {
    float x, y; asm("mov.b64 {%0, %1}, %2;" : "=f"(x), "=f"(y) : "l"(a)); return x + y;
}
__device__ __forceinline__ float tanhap(float x) {
    float y; asm("tanh.approx.f32 %0, %1;" : "=f"(y) : "f"(x)); return y;
}
__device__ __forceinline__ float sigap(float x) {
    return fmaf(0.5f, tanhap(0.5f * x), 0.5f);
}

__global__ __launch_bounds__(NTH, 1)
void lstm2_kernel(const float* __restrict__ input,
                  const float* __restrict__ W_ih1,
                  const float* __restrict__ W_hh1,
                  const float* __restrict__ b_ih1,
                  const float* __restrict__ b_hh1,
                  const float* __restrict__ W_ih2,
                  const float* __restrict__ W_hh2,
                  const float* __restrict__ b_ih2,
                  const float* __restrict__ b_hh2,
                  const float* __restrict__ W_lin,
                  const float* __restrict__ b_lin,
                  float* __restrict__ out)
{
    __shared__ __align__(16) float hbuf[2*BHP + 8 + 2*BHP];
    __shared__ float xall[4*TT];

    float* const h1b = hbuf;
    float* const h2b = hbuf + 2*BHP + 8;

    const int tid  = threadIdx.x;
    const int lane = tid & 31;
    const int wid  = tid >> 5;
    const int s    = wid & 3;     // SMSP
    const int slot = wid >> 2;    // 0,1,2
    const int row0 = blockIdx.x * 4;

    const unsigned pmask = 0x3u << (lane & 30);
    const unsigned qmask = 0xFu << (lane & 28);

    // ---- SMSP-balanced role decode ----
    // L1: 51 (unit) x 2 (ks) pairs. SMSP s owns units [ubase, ubase+P1).
    // L2: 51 quads (unit x {mat,ks}). SMSP s owns quads [qbase, qbase+NQ).
    const int ubase = 13 * s;                 // s=3 -> 39 (12 units)
    const int P1    = (s < 3) ? 13 : 12;
    const int NQ    = (s < 3) ? 13 : 12;

    bool isL1 = false, isL2 = false, isOut = false;
    int unit = 0, ks = 0, mat = 0;
    if (slot == 0) {                          // L1 pairs
        if (lane < 2 * P1) { isL1 = true; unit = ubase + (lane >> 1); ks = lane & 1; }
    } else if (slot == 1) {                   // first 8 L2 quads of this SMSP
        isL2 = true;
        unit = ubase + (lane >> 2);
        mat  = (lane >> 1) & 1;
        ks   = lane & 1;
    } else {                                  // remaining quads (+ out-head in warp 11)
        const int nq2 = NQ - 8;               // 5 (s<3) or 4 (s=3)
        if (lane < 4 * nq2) {
            isL2 = true;
            unit = ubase + 8 + (lane >> 2);
            mat  = (lane >> 1) & 1;
            ks   = lane & 1;
        } else if (s == 3 && lane >= 16 && lane < 24) {
            isOut = true;
        }
    }

    // ---- init smem ----
    for (int i = tid; i < 2*BHP + 8 + 2*BHP; i += NTH) hbuf[i] = 0.0f;
    for (int i = tid; i < 4*TT; i += NTH) {
        const int b = i >> 9;
        const int t = i & (TT - 1);
        xall[i] = input[(row0 + b)*TT + t];
    }

    // ---- weights -> registers: 4 gate rows x k-half as f32x2 ----
    ull w2[4][14];
    float bz[4] = {0,0,0,0}, wx[4] = {0,0,0,0};
    if (isL1 || isL2) {
        const float* W = isL1 ? W_hh1 : (mat ? W_hh2 : W_ih2);
        #pragma unroll
        for (int g = 0; g < 4; ++g) {
            const int r = unit + 51*g;
            #pragma unroll
            for (int m = 0; m < 14; ++m) {
                const int k = ks*28 + 2*m;
                const float lo = (k   < H) ? W[r*H + k]     : 0.0f;
                const float hi = (k+1 < H) ? W[r*H + k + 1] : 0.0f;
                w2[g][m] = pack2(lo, hi);
            }
            if (isL1) { bz[g] = b_ih1[r] + b_hh1[r]; wx[g] = W_ih1[r]; }
            else      { bz[g] = b_ih2[r] + b_hh2[r]; }
        }
    }

    // ---- out-head weights (warp 11 lanes 16-23) ----
    float wo[26]; float blin = 0.0f; int ob = 0, half = 0;
    if (isOut) {
        const int o = lane - 16;
        ob = o >> 1; half = o & 1;
        #pragma unroll
        for (int m = 0; m < 26; ++m) {
            const int j = half*26 + m;
            wo[m] = (j < H) ? W_lin[j] : 0.0f;
        }
        blin = b_lin[0];
    }

    float c1[2] = {0.f, 0.f};   // L1: two (unit,b) cells
    float c2 = 0.f;             // L2 final holder

    __syncthreads();

    for (int t = 0; t < NITER; ++t) {
        const int p = t & 1;
        float* const h1r = h1b + p*BHP;        // h1(t-1)
        float* const h1w = h1b + (p^1)*BHP;    // h1(t)
        float* const h2r = h2b + p*BHP;        // h2(t-2)
        float* const h2w = h2b + (p^1)*BHP;    // h2(t-1)

        if (isL1) {
            if (t < TT) {
                ull acc[4][4];
                #pragma unroll
                for (int g = 0; g < 4; ++g)
                    { acc[g][0]=0ull; acc[g][1]=0ull; acc[g][2]=0ull; acc[g][3]=0ull; }
                const float* hp = h1r + ks*28;
                #pragma unroll
                for (int j = 0; j < 7; ++j) {
                    const ulonglong2 u0 = *reinterpret_cast<const ulonglong2*>(hp + 0*HP + 4*j);
                    const ulonglong2 u1 = *reinterpret_cast<const ulonglong2*>(hp + 1*HP + 4*j);
                    const ulonglong2 u2 = *reinterpret_cast<const ulonglong2*>(hp + 2*HP + 4*j);
                    const ulonglong2 u3 = *reinterpret_cast<const ulonglong2*>(hp + 3*HP + 4*j);
                    #pragma unroll
                    for (int g = 0; g < 4; ++g) {
                        acc[g][0] = fma2(w2[g][2*j],   u0.x, acc[g][0]);
                        acc[g][0] = fma2(w2[g][2*j+1], u0.y, acc[g][0]);
                        acc[g][1] = fma2(w2[g][2*j],   u1.x, acc[g][1]);
                        acc[g][1] = fma2(w2[g][2*j+1], u1.y, acc[g][1]);
                        acc[g][2] = fma2(w2[g][2*j],   u2.x, acc[g][2]);
                        acc[g][2] = fma2(w2[g][2*j+1], u2.y, acc[g][2]);
                        acc[g][3] = fma2(w2[g][2*j],   u3.x, acc[g][3]);
                        acc[g][3] = fma2(w2[g][2*j+1], u3.y, acc[g][3]);
                    }
                }
                float fin[4][2];
                #pragma unroll
                for (int g = 0; g < 4; ++g)
                    #pragma unroll
                    for (int lb = 0; lb < 2; ++lb) {
                        const float mine  = sum2(ks ? acc[g][2+lb] : acc[g][lb]);
                        const float other = sum2(ks ? acc[g][lb]   : acc[g][2+lb]);
                        fin[g][lb] = mine + __shfl_xor_sync(pmask, other, 1);
                    }
                #pragma unroll
                for (int lb = 0; lb < 2; ++lb) {
                    const int b = 2*ks + lb;
                    const float xv = xall[b*TT + t];
                    const float zi = fmaf(xv, wx[0], fin[0][lb] + bz[0]);
                    const float zf = fmaf(xv, wx[1], fin[1][lb] + bz[1]);
                    const float zg = fmaf(xv, wx[2], fin[2][lb] + bz[2]);
                    const float zo = fmaf(xv, wx[3], fin[3][lb] + bz[3]);
                    const float ig = sigap(zi), fg = sigap(zf);
                    const float gg = tanhap(zg), og = sigap(zo);
                    c1[lb] = fmaf(fg, c1[lb], ig*gg);
                    h1w[b*HP + unit] = og * tanhap(c1[lb]);
                }
            }
        } else if (isL2) {
            if (t >= 1 && t <= TT) {
                ull acc[4][4];
                #pragma unroll
                for (int g = 0; g < 4; ++g)
                    { acc[g][0]=0ull; acc[g][1]=0ull; acc[g][2]=0ull; acc[g][3]=0ull; }
                const float* hp = (mat ? h2r : h1r) + ks*28;
                #pragma unroll
                for (int j = 0; j < 7; ++j) {
                    const ulonglong2 u0 = *reinterpret_cast<const ulonglong2*>(hp + 0*HP + 4*j);
                    const ulonglong2 u1 = *reinterpret_cast<const ulonglong2*>(hp + 1*HP + 4*j);
                    const ulonglong2 u2 = *reinterpret_cast<const ulonglong2*>(hp + 2*HP + 4*j);
                    const ulonglong2 u3 = *reinterpret_cast<const ulonglong2*>(hp + 3*HP + 4*j);
                    #pragma unroll
                    for (int g = 0; g < 4; ++g) {
                        acc[g][0] = fma2(w2[g][2*j],   u0.x, acc[g][0]);
                        acc[g][0] = fma2(w2[g][2*j+1], u0.y, acc[g][0]);
                        acc[g][1] = fma2(w2[g][2*j],   u1.x, acc[g][1]);
                        acc[g][1] = fma2(w2[g][2*j+1], u1.y, acc[g][1]);
                        acc[g][2] = fma2(w2[g][2*j],   u2.x, acc[g][2]);
                        acc[g][2] = fma2(w2[g][2*j+1], u2.y, acc[g][2]);
                        acc[g][3] = fma2(w2[g][2*j],   u3.x, acc[g][3]);
                        acc[g][3] = fma2(w2[g][2*j+1], u3.y, acc[g][3]);
                    }
                }
                float fin1[4][2];
                #pragma unroll
                for (int g = 0; g < 4; ++g)
                    #pragma unroll
                    for (int lb = 0; lb < 2; ++lb) {
                        const float mine  = sum2(ks ? acc[g][2+lb] : acc[g][lb]);
                        const float other = sum2(ks ? acc[g][lb]   : acc[g][2+lb]);
                        fin1[g][lb] = mine + __shfl_xor_sync(pmask, other, 1);
                    }
                const int b = 2*ks + mat;
                float zf4[4];
                #pragma unroll
                for (int g = 0; g < 4; ++g) {
                    const float mine  = mat ? fin1[g][1] : fin1[g][0];
                    const float other = mat ? fin1[g][0] : fin1[g][1];
                    zf4[g] = mine + __shfl_xor_sync(qmask, other, 2) + bz[g];
                }
                const float ig = sigap(zf4[0]), fg = sigap(zf4[1]);
                const float gg = tanhap(zf4[2]), og = sigap(zf4[3]);
                c2 = fmaf(fg, c2, ig*gg);
                h2w[b*HP + unit] = og * tanhap(c2);
            }
        } else if (isOut) {
            if (t >= 2) {
                float v = 0.f;
                #pragma unroll
                for (int m = 0; m < 26; ++m)
                    v = fmaf(h2r[ob*HP + half*26 + m], wo[m], v);
                v += __shfl_xor_sync(pmask, v, 1);
                if (half == 0) out[(row0 + ob)*TT + (t - 2)] = v + blin;
            }
        }
        __syncthreads();
    }
}

extern "C" void kernel_launch(void* const* d_in, const int* in_sizes, int n_in,
                              void* d_out, int out_size)
{
    const float* input = (const float*)d_in[0];
    const float* W_ih1 = (const float*)d_in[1];
    const float* W_hh1 = (const float*)d_in[2];
    const float* b_ih1 = (const float*)d_in[3];
    const float* b_hh1 = (const float*)d_in[4];
    const float* W_ih2 = (const float*)d_in[5];
    const float* W_hh2 = (const float*)d_in[6];
    const float* b_ih2 = (const float*)d_in[7];
    const float* b_hh2 = (const float*)d_in[8];
    const float* W_lin = (const float*)d_in[9];
    const float* b_lin = (const float*)d_in[10];
    float* out = (float*)d_out;

    lstm2_kernel<<<NBLK, NTH>>>(input, W_ih1, W_hh1, b_ih1, b_hh1,
                                W_ih2, W_hh2, b_ih2, b_hh2,
                                W_lin, b_lin, out);
}